// round 10
// baseline (speedup 1.0000x reference)
#include <cuda_runtime.h>
#include <cuda_fp16.h>

#define HH 8
#define NN 2048
#define ROWS (HH * NN)               // 16384
#define GAMMA 0.9f
#define TOL2 1e-6f                   // ||dx|| < 1e-3 (see error budget above)
#define MAX_ITER 50

#define NBLOCKS 148
#define NTHREADS 1024
#define TILES 1024                   // 16-row tiles over all heads
#define NFULL 136                    // CTAs 0..135 own 7 tiles; 136..147 own 6
#define FRAGS_PER_TILE 4096          // 128 k-tiles * 32 lanes (uint4 each)
#define STAGE_W 1028                 // padded half2-words per staged row

// Device-global scratch (no runtime allocation allowed)
__device__ __align__(16) uint4 g_Ahf[(size_t)TILES * FRAGS_PER_TILE]; // fp16 A, frag layout
__device__ __align__(16) float    g_xf[2][ROWS];      // fp32 iterate (ping-pong)
__device__ __align__(16) unsigned g_xh[2][ROWS / 2];  // same iterate pre-packed half2
__device__ float    g_bsum[2][NBLOCKS];
__device__ unsigned g_arrive = 0;
__device__ unsigned g_gen    = 0;

__device__ __forceinline__ void grid_barrier() {
    __syncthreads();
    if (threadIdx.x == 0) {
        volatile unsigned* genp = &g_gen;
        unsigned my = *genp;
        __threadfence();
        unsigned prev = atomicAdd(&g_arrive, 1u);
        if (prev == NBLOCKS - 1) {
            atomicExch(&g_arrive, 0u);
            __threadfence();
            atomicAdd(&g_gen, 1u);
        } else {
            while (*genp == my) { }
        }
        __threadfence();
    }
    __syncthreads();
}

__device__ __forceinline__ void mma16816(float& c0, float& c1, float& c2, float& c3,
                                         uint4 a, unsigned b0, unsigned b1) {
    asm volatile(
        "mma.sync.aligned.m16n8k16.row.col.f32.f16.f16.f32 "
        "{%0,%1,%2,%3}, {%4,%5,%6,%7}, {%8,%9}, {%0,%1,%2,%3};\n"
        : "+f"(c0), "+f"(c1), "+f"(c2), "+f"(c3)
        : "r"(a.x), "r"(a.y), "r"(a.z), "r"(a.w), "r"(b0), "r"(b1));
}

// Dynamic smem: [ stage: 16*STAGE_W words ][ xh: 2048 words (<=2 heads of x) ]
extern __shared__ unsigned s_dyn_u[];

__global__ void __launch_bounds__(NTHREADS, 1)
fp_kernel(const float* __restrict__ A, const float* __restrict__ b,
          float* __restrict__ out)
{
    unsigned* stage = s_dyn_u;                       // conversion staging
    unsigned* xh    = s_dyn_u + 16 * STAGE_W;        // x (needed heads) as half2

    __shared__ float spart[7][4][16];                // row-tile x kq x 16-row partials
    __shared__ float xfown[2][128];                  // own-row fp32 iterate by parity
    __shared__ float bown[128];                      // own-row bias
    __shared__ float red32[32];
    __shared__ float totsh;

    const int tid  = threadIdx.x;
    const int warp = tid >> 5;
    const int lane = tid & 31;
    const int l4   = lane & 3;
    const int cta  = blockIdx.x;

    int start, count;
    if (cta < NFULL) { start = cta * 7;                       count = 7; }
    else             { start = NFULL * 7 + (cta - NFULL) * 6; count = 6; }
    const int nrows = count * 16;
    const int rbase = start * 16;
    const int h0 = rbase >> 11;                       // first head this CTA touches
    const int h1 = (rbase + nrows - 1) >> 11;         // last head (h0 or h0+1)
    const int nwords = (h1 - h0 + 1) * (NN / 2);      // <= 2048 half2 words

    // ================= Phase 1: coalesced conversion via smem staging ========
    for (int g = 0; g < count; ++g) {
        const int rt = start + g;
        const float4* Asrc = reinterpret_cast<const float4*>(A + (size_t)rt * 16 * NN);
        for (int i = tid; i < 16 * NN / 4; i += NTHREADS) {   // coalesced float4 reads
            int row = i >> 9;
            int c4  = i & 511;
            float4 v = Asrc[i];
            __half2 q0 = __floats2half2_rn(v.x, v.y);
            __half2 q1 = __floats2half2_rn(v.z, v.w);
            stage[row * STAGE_W + c4 * 2]     = *reinterpret_cast<unsigned*>(&q0);
            stage[row * STAGE_W + c4 * 2 + 1] = *reinterpret_cast<unsigned*>(&q1);
        }
        __syncthreads();
        uint4* dst = g_Ahf + (size_t)rt * FRAGS_PER_TILE;
        for (int i = tid; i < FRAGS_PER_TILE; i += NTHREADS) { // coalesced 512B/warp out
            int kb = i >> 5, ln = i & 31;
            int r = ln >> 2, j = ln & 3;
            int w = r * STAGE_W + kb * 8 + j;
            uint4 u;
            u.x = stage[w];
            u.y = stage[w + 8 * STAGE_W];
            u.z = stage[w + 4];
            u.w = stage[w + 8 * STAGE_W + 4];
            dst[i] = u;
        }
        __syncthreads();
    }

    // ================= Phase 2 init: x0 = 0, x1 = tanh(b) ====================
    float lsum0 = 0.f;
    if (tid < nrows) {
        int grow = rbase + tid;
        float bb = b[grow];
        bown[tid] = bb;
        float y = tanhf(bb);                 // gamma*A@0 + b = b
        g_xf[1][grow] = y;
        g_xf[0][grow] = 0.f;
        xfown[1][tid] = y;
        lsum0 = y * y;
    }
    #pragma unroll
    for (int o = 16; o > 0; o >>= 1)
        lsum0 += __shfl_xor_sync(0xFFFFFFFFu, lsum0, o);
    if (lane == 0) red32[warp] = lsum0;
    __syncthreads();
    if (tid < nrows / 2) {                   // pack own rows as half2
        __half2 q = __floats2half2_rn(xfown[1][2 * tid], xfown[1][2 * tid + 1]);
        g_xh[1][(rbase >> 1) + tid] = *reinterpret_cast<unsigned*>(&q);
    }
    if (warp == 0) {
        float s = red32[lane];
        #pragma unroll
        for (int o = 16; o > 0; o >>= 1)
            s += __shfl_xor_sync(0xFFFFFFFFu, s, o);
        if (lane == 0) g_bsum[1][cta] = s;
    }
    grid_barrier();

    // ================= Phase 2: fixed-point loop =============================
    int zpar;
    for (int k = 1;; ++k) {
        const int pin = k & 1;               // parity of x_k

        // gather x_k for the heads this CTA needs (pre-packed half2, L2-hot)
        for (int i = tid; i < nwords; i += NTHREADS)
            xh[i] = __ldcg(&g_xh[pin][h0 * (NN / 2) + i]);

        // decision on transition (k-1)->k: fixed-order sum of 148 block partials
        if (warp == 0) {
            float s = 0.f;
            #pragma unroll
            for (int q = 0; q < 5; ++q) {
                int idx = lane + 32 * q;
                if (idx < NBLOCKS) s += __ldcg(&g_bsum[pin][idx]);
            }
            #pragma unroll
            for (int o = 16; o > 0; o >>= 1)
                s += __shfl_xor_sync(0xFFFFFFFFu, s, o);
            if (lane == 0) totsh = s;
        }
        __syncthreads();
        float tot = totsh;
        if (tot < TOL2)    { zpar = pin ^ 1; break; }   // z* = x_{k-1}
        if (k == MAX_ITER) { zpar = 0;       break; }   // z* = x_50

        // HMMA matvec: warp = row-tile g x K-quarter kq (512 K), depth-2 prefetch
        {
            const int g  = warp >> 2;
            const int kq = warp & 3;
            if (g < count) {
                const int rt   = start + g;
                const int head = rt >> 7;
                const uint4* __restrict__ Af =
                    g_Ahf + (size_t)rt * FRAGS_PER_TILE + (kq * 32) * 32 + lane;
                const unsigned* xb = xh + (head - h0) * 1024 + kq * 256;
                float c0 = 0.f, c1 = 0.f, c2 = 0.f, c3 = 0.f;
                uint4 a = Af[0];
                #pragma unroll 8
                for (int t = 0; t < 32; ++t) {
                    uint4 an = Af[((t + 1) & 31) * 32];     // in-bounds rotate
                    unsigned b0 = xb[t * 8 + l4];
                    unsigned b1 = xb[t * 8 + 4 + l4];
                    mma16816(c0, c1, c2, c3, a, b0, b1);
                    a = an;
                }
                if (l4 == 0) {               // D col 0: c0 -> row lane/4, c2 -> +8
                    spart[g][kq][lane >> 2]       = c0;
                    spart[g][kq][(lane >> 2) + 8] = c2;
                }
            }
        }
        __syncthreads();

        // finish own rows: combine K-quarters, tanh, diff, export
        const int pout = pin ^ 1;
        float lsum = 0.f;
        if (tid < nrows) {
            float s = spart[tid >> 4][0][tid & 15] + spart[tid >> 4][1][tid & 15]
                    + spart[tid >> 4][2][tid & 15] + spart[tid >> 4][3][tid & 15];
            float y = tanhf(GAMMA * s + bown[tid]);
            float d = xfown[pin][tid] - y;
            lsum = d * d;
            xfown[pout][tid] = y;
            g_xf[pout][rbase + tid] = y;
        }
        #pragma unroll
        for (int o = 16; o > 0; o >>= 1)
            lsum += __shfl_xor_sync(0xFFFFFFFFu, lsum, o);
        if (lane == 0) red32[warp] = lsum;
        __syncthreads();
        if (tid < nrows / 2) {               // pack own rows as half2
            __half2 q = __floats2half2_rn(xfown[pout][2 * tid], xfown[pout][2 * tid + 1]);
            g_xh[pout][(rbase >> 1) + tid] = *reinterpret_cast<unsigned*>(&q);
        }
        if (warp == 0) {
            float s = red32[lane];
            #pragma unroll
            for (int o = 16; o > 0; o >>= 1)
                s += __shfl_xor_sync(0xFFFFFFFFu, s, o);
            if (lane == 0) g_bsum[pout][cta] = s;
        }
        grid_barrier();                      // publish x_{k+1} + partials
    }
    // g_xf[zpar] = z_star (break semantics match the torch loop)

    // ================= Phase 3: final step with ORIGINAL fp32 A ==============
    {
        const int sub  = lane >> 3;          // 0..3 (row within warp)
        const int j    = lane & 7;           // 0..7 (K-lane)
        const int rloc = warp * 4 + sub;
        if (rloc < nrows) {
            const int grow = rbase + rloc;
            const int head = grow >> 11;
            const float4* A4 = reinterpret_cast<const float4*>(A + (size_t)grow * NN);
            const float4* x4 = reinterpret_cast<const float4*>(g_xf[zpar] + head * NN);
            float acc0 = 0.f, acc1 = 0.f;
            #pragma unroll 8
            for (int s = 0; s < 32; ++s) {
                float4 aa = A4[s * 16 + 2 * j];
                float4 xa = __ldcg(x4 + s * 16 + 2 * j);
                float4 ab = A4[s * 16 + 2 * j + 1];
                float4 xb2 = __ldcg(x4 + s * 16 + 2 * j + 1);
                acc0 = fmaf(aa.x, xa.x, acc0);
                acc0 = fmaf(aa.y, xa.y, acc0);
                acc0 = fmaf(aa.z, xa.z, acc0);
                acc0 = fmaf(aa.w, xa.w, acc0);
                acc1 = fmaf(ab.x, xb2.x, acc1);
                acc1 = fmaf(ab.y, xb2.y, acc1);
                acc1 = fmaf(ab.z, xb2.z, acc1);
                acc1 = fmaf(ab.w, xb2.w, acc1);
            }
            float acc = acc0 + acc1;
            acc += __shfl_xor_sync(0xFFFFFFFFu, acc, 1);
            acc += __shfl_xor_sync(0xFFFFFFFFu, acc, 2);
            acc += __shfl_xor_sync(0xFFFFFFFFu, acc, 4);
            if (j == 0)
                out[grow] = tanhf(GAMMA * acc + bown[rloc]);
        }
    }
}

extern "C" void kernel_launch(void* const* d_in, const int* in_sizes, int n_in,
                              void* d_out, int out_size)
{
    const float* A = (const float*)d_in[0];
    const float* b = (const float*)d_in[1];
    if (n_in >= 2 && in_sizes[0] == ROWS) {   // defensive: A is the 33.5M-elem input
        A = (const float*)d_in[1];
        b = (const float*)d_in[0];
    }

    const int smem = (16 * STAGE_W + 2048) * (int)sizeof(unsigned);  // 73984 B
    cudaFuncSetAttribute(fp_kernel, cudaFuncAttributeMaxDynamicSharedMemorySize, smem);
    fp_kernel<<<NBLOCKS, NTHREADS, smem>>>(A, b, (float*)d_out);
}

// round 11
// speedup vs baseline: 1.0302x; 1.0302x over previous
#include <cuda_runtime.h>
#include <cuda_fp16.h>

#define HH 8
#define NN 2048
#define ROWS (HH * NN)               // 16384
#define GAMMA 0.9f
#define TOL2 1e-6f                   // ||dx|| < 1e-3 (see error budget above)
#define MAX_ITER 50

#define NBLOCKS 148
#define NTHREADS 1024
#define TILES 1024                   // 16-row tiles over all heads
#define NFULL 136                    // CTAs 0..135 own 7 tiles; 136..147 own 6
#define FRAGS_PER_TILE 4096          // 128 k-tiles * 32 lanes (uint4 each)
#define STAGE_W 1028                 // padded half2-words per staged row

// Device-global scratch (no runtime allocation allowed)
__device__ __align__(16) uint4 g_Ahf[(size_t)TILES * FRAGS_PER_TILE]; // fp16 A, frag layout
__device__ __align__(16) float    g_xf[2][ROWS];      // fp32 iterate (ping-pong)
__device__ __align__(16) unsigned g_xh[2][ROWS / 2];  // same iterate pre-packed half2
__device__ float    g_bsum[2][NBLOCKS];
__device__ unsigned g_arrive = 0;
__device__ unsigned g_gen    = 0;

__device__ __forceinline__ void grid_barrier() {
    __syncthreads();
    if (threadIdx.x == 0) {
        volatile unsigned* genp = &g_gen;
        unsigned my = *genp;
        __threadfence();
        unsigned prev = atomicAdd(&g_arrive, 1u);
        if (prev == NBLOCKS - 1) {
            atomicExch(&g_arrive, 0u);
            __threadfence();
            atomicAdd(&g_gen, 1u);
        } else {
            while (*genp == my) { }
        }
        __threadfence();
    }
    __syncthreads();
}

__device__ __forceinline__ void mma16816(float& c0, float& c1, float& c2, float& c3,
                                         uint4 a, unsigned b0, unsigned b1) {
    asm volatile(
        "mma.sync.aligned.m16n8k16.row.col.f32.f16.f16.f32 "
        "{%0,%1,%2,%3}, {%4,%5,%6,%7}, {%8,%9}, {%0,%1,%2,%3};\n"
        : "+f"(c0), "+f"(c1), "+f"(c2), "+f"(c3)
        : "r"(a.x), "r"(a.y), "r"(a.z), "r"(a.w), "r"(b0), "r"(b1));
}

// Dynamic smem: [ stage: 16*STAGE_W words ][ xh: 2048 words (<=2 heads of x) ]
extern __shared__ unsigned s_dyn_u[];

__global__ void __launch_bounds__(NTHREADS, 1)
fp_kernel(const float* __restrict__ A, const float* __restrict__ b,
          float* __restrict__ out)
{
    unsigned* stage = s_dyn_u;                       // conversion staging
    unsigned* xh    = s_dyn_u + 16 * STAGE_W;        // x (needed heads) as half2

    __shared__ float spart[7][4][16];                // row-tile x kq x 16-row partials
    __shared__ float xfown[2][128];                  // own-row fp32 iterate by parity
    __shared__ float bown[128];                      // own-row bias
    __shared__ float red32[32];
    __shared__ float totsh;

    const int tid  = threadIdx.x;
    const int warp = tid >> 5;
    const int lane = tid & 31;
    const int l4   = lane & 3;
    const int cta  = blockIdx.x;

    int start, count;
    if (cta < NFULL) { start = cta * 7;                       count = 7; }
    else             { start = NFULL * 7 + (cta - NFULL) * 6; count = 6; }
    const int nrows = count * 16;
    const int rbase = start * 16;
    const int h0 = rbase >> 11;                       // first head this CTA touches
    const int h1 = (rbase + nrows - 1) >> 11;         // last head (h0 or h0+1)
    const int nwords = (h1 - h0 + 1) * (NN / 2);      // <= 2048 half2 words

    // ================= Phase 1: coalesced conversion via smem staging ========
    for (int g = 0; g < count; ++g) {
        const int rt = start + g;
        const float4* Asrc = reinterpret_cast<const float4*>(A + (size_t)rt * 16 * NN);
        for (int i = tid; i < 16 * NN / 4; i += NTHREADS) {   // coalesced float4 reads
            int row = i >> 9;
            int c4  = i & 511;
            float4 v = Asrc[i];
            __half2 q0 = __floats2half2_rn(v.x, v.y);
            __half2 q1 = __floats2half2_rn(v.z, v.w);
            stage[row * STAGE_W + c4 * 2]     = *reinterpret_cast<unsigned*>(&q0);
            stage[row * STAGE_W + c4 * 2 + 1] = *reinterpret_cast<unsigned*>(&q1);
        }
        __syncthreads();
        uint4* dst = g_Ahf + (size_t)rt * FRAGS_PER_TILE;
        for (int i = tid; i < FRAGS_PER_TILE; i += NTHREADS) { // coalesced 512B/warp out
            int kb = i >> 5, ln = i & 31;
            int r = ln >> 2, j = ln & 3;
            int w = r * STAGE_W + kb * 8 + j;
            uint4 u;
            u.x = stage[w];
            u.y = stage[w + 8 * STAGE_W];
            u.z = stage[w + 4];
            u.w = stage[w + 8 * STAGE_W + 4];
            dst[i] = u;
        }
        __syncthreads();
    }

    // ================= Phase 2 init: x0 = 0, x1 = tanh(b) ====================
    float lsum0 = 0.f;
    if (tid < nrows) {
        int grow = rbase + tid;
        float bb = b[grow];
        bown[tid] = bb;
        float y = tanhf(bb);                 // gamma*A@0 + b = b
        g_xf[1][grow] = y;
        g_xf[0][grow] = 0.f;
        xfown[1][tid] = y;
        lsum0 = y * y;
    }
    #pragma unroll
    for (int o = 16; o > 0; o >>= 1)
        lsum0 += __shfl_xor_sync(0xFFFFFFFFu, lsum0, o);
    if (lane == 0) red32[warp] = lsum0;
    __syncthreads();
    if (tid < nrows / 2) {                   // pack own rows as half2
        __half2 q = __floats2half2_rn(xfown[1][2 * tid], xfown[1][2 * tid + 1]);
        g_xh[1][(rbase >> 1) + tid] = *reinterpret_cast<unsigned*>(&q);
    }
    if (warp == 0) {
        float s = red32[lane];
        #pragma unroll
        for (int o = 16; o > 0; o >>= 1)
            s += __shfl_xor_sync(0xFFFFFFFFu, s, o);
        if (lane == 0) g_bsum[1][cta] = s;
    }
    grid_barrier();

    // ================= Phase 2: fixed-point loop =============================
    int zpar;
    for (int k = 1;; ++k) {
        const int pin = k & 1;               // parity of x_k

        // gather x_k for the heads this CTA needs (pre-packed half2, L2-hot)
        for (int i = tid; i < nwords; i += NTHREADS)
            xh[i] = __ldcg(&g_xh[pin][h0 * (NN / 2) + i]);

        // decision on transition (k-1)->k: fixed-order sum of 148 block partials
        if (warp == 0) {
            float s = 0.f;
            #pragma unroll
            for (int q = 0; q < 5; ++q) {
                int idx = lane + 32 * q;
                if (idx < NBLOCKS) s += __ldcg(&g_bsum[pin][idx]);
            }
            #pragma unroll
            for (int o = 16; o > 0; o >>= 1)
                s += __shfl_xor_sync(0xFFFFFFFFu, s, o);
            if (lane == 0) totsh = s;
        }
        __syncthreads();
        float tot = totsh;
        if (tot < TOL2)    { zpar = pin ^ 1; break; }   // z* = x_{k-1}
        if (k == MAX_ITER) { zpar = 0;       break; }   // z* = x_50

        // HMMA matvec: warp = row-tile g x K-quarter kq (512 K), depth-2 prefetch
        {
            const int g  = warp >> 2;
            const int kq = warp & 3;
            if (g < count) {
                const int rt   = start + g;
                const int head = rt >> 7;
                const uint4* __restrict__ Af =
                    g_Ahf + (size_t)rt * FRAGS_PER_TILE + (kq * 32) * 32 + lane;
                const unsigned* xb = xh + (head - h0) * 1024 + kq * 256;
                float c0 = 0.f, c1 = 0.f, c2 = 0.f, c3 = 0.f;
                uint4 a = Af[0];
                #pragma unroll 8
                for (int t = 0; t < 32; ++t) {
                    uint4 an = Af[((t + 1) & 31) * 32];     // in-bounds rotate
                    unsigned b0 = xb[t * 8 + l4];
                    unsigned b1 = xb[t * 8 + 4 + l4];
                    mma16816(c0, c1, c2, c3, a, b0, b1);
                    a = an;
                }
                if (l4 == 0) {               // D col 0: c0 -> row lane/4, c2 -> +8
                    spart[g][kq][lane >> 2]       = c0;
                    spart[g][kq][(lane >> 2) + 8] = c2;
                }
            }
        }
        __syncthreads();

        // finish own rows: combine K-quarters, tanh, diff, export
        const int pout = pin ^ 1;
        float lsum = 0.f;
        if (tid < nrows) {
            float s = spart[tid >> 4][0][tid & 15] + spart[tid >> 4][1][tid & 15]
                    + spart[tid >> 4][2][tid & 15] + spart[tid >> 4][3][tid & 15];
            float y = tanhf(GAMMA * s + bown[tid]);
            float d = xfown[pin][tid] - y;
            lsum = d * d;
            xfown[pout][tid] = y;
            g_xf[pout][rbase + tid] = y;
        }
        #pragma unroll
        for (int o = 16; o > 0; o >>= 1)
            lsum += __shfl_xor_sync(0xFFFFFFFFu, lsum, o);
        if (lane == 0) red32[warp] = lsum;
        __syncthreads();
        if (tid < nrows / 2) {               // pack own rows as half2
            __half2 q = __floats2half2_rn(xfown[pout][2 * tid], xfown[pout][2 * tid + 1]);
            g_xh[pout][(rbase >> 1) + tid] = *reinterpret_cast<unsigned*>(&q);
        }
        if (warp == 0) {
            float s = red32[lane];
            #pragma unroll
            for (int o = 16; o > 0; o >>= 1)
                s += __shfl_xor_sync(0xFFFFFFFFu, s, o);
            if (lane == 0) g_bsum[pout][cta] = s;
        }
        grid_barrier();                      // publish x_{k+1} + partials
    }
    // g_xf[zpar] = z_star (break semantics match the torch loop)

    // ================= Phase 3: final step with ORIGINAL fp32 A ==============
    {
        const int sub  = lane >> 3;          // 0..3 (row within warp)
        const int j    = lane & 7;           // 0..7 (K-lane)
        const int rloc = warp * 4 + sub;
        if (rloc < nrows) {
            const int grow = rbase + rloc;
            const int head = grow >> 11;
            const float4* A4 = reinterpret_cast<const float4*>(A + (size_t)grow * NN);
            const float4* x4 = reinterpret_cast<const float4*>(g_xf[zpar] + head * NN);
            float acc0 = 0.f, acc1 = 0.f;
            #pragma unroll 8
            for (int s = 0; s < 32; ++s) {
                float4 aa = A4[s * 16 + 2 * j];
                float4 xa = __ldcg(x4 + s * 16 + 2 * j);
                float4 ab = A4[s * 16 + 2 * j + 1];
                float4 xb2 = __ldcg(x4 + s * 16 + 2 * j + 1);
                acc0 = fmaf(aa.x, xa.x, acc0);
                acc0 = fmaf(aa.y, xa.y, acc0);
                acc0 = fmaf(aa.z, xa.z, acc0);
                acc0 = fmaf(aa.w, xa.w, acc0);
                acc1 = fmaf(ab.x, xb2.x, acc1);
                acc1 = fmaf(ab.y, xb2.y, acc1);
                acc1 = fmaf(ab.z, xb2.z, acc1);
                acc1 = fmaf(ab.w, xb2.w, acc1);
            }
            float acc = acc0 + acc1;
            acc += __shfl_xor_sync(0xFFFFFFFFu, acc, 1);
            acc += __shfl_xor_sync(0xFFFFFFFFu, acc, 2);
            acc += __shfl_xor_sync(0xFFFFFFFFu, acc, 4);
            if (j == 0)
                out[grow] = tanhf(GAMMA * acc + bown[rloc]);
        }
    }
}

extern "C" void kernel_launch(void* const* d_in, const int* in_sizes, int n_in,
                              void* d_out, int out_size)
{
    const float* A = (const float*)d_in[0];
    const float* b = (const float*)d_in[1];
    if (n_in >= 2 && in_sizes[0] == ROWS) {   // defensive: A is the 33.5M-elem input
        A = (const float*)d_in[1];
        b = (const float*)d_in[0];
    }

    const int smem = (16 * STAGE_W + 2048) * (int)sizeof(unsigned);  // 73984 B
    cudaFuncSetAttribute(fp_kernel, cudaFuncAttributeMaxDynamicSharedMemorySize, smem);
    fp_kernel<<<NBLOCKS, NTHREADS, smem>>>(A, b, (float*)d_out);
}